// round 15
// baseline (speedup 1.0000x reference)
#include <cuda_runtime.h>
#include <math.h>
#include <cstdint>

#define D_MODEL 1024
#define DHEAD   64
#define NHEADS  16
#define DHID    4096
#define BATCH   2
#define SEQ     2048
#define MROWS   (BATCH*SEQ)   // 4096
#define LN_EPS  1e-5f

// ---------------- scratch (device globals; no allocations allowed) ----------
__device__ float g_QKV [(size_t)MROWS*3072];
__device__ float g_CTX [MROWS*D_MODEL];
__device__ float g_PRJ [MROWS*D_MODEL];
__device__ float g_X1  [MROWS*D_MODEL];
__device__ float g_X1r [MROWS*D_MODEL];
__device__ float g_T   [MROWS*D_MODEL];
__device__ float g_Xr  [MROWS*D_MODEL];
__device__ float g_H   [(size_t)MROWS*DHID];
__device__ float g_WTqkv[(size_t)3*D_MODEL*D_MODEL];
__device__ float g_WTo [D_MODEL*D_MODEL];
__device__ float g_WT1 [(size_t)DHID*D_MODEL];
__device__ float g_WT2 [(size_t)D_MODEL*DHID];
__device__ float g_Bqkv[3072];

// ---------------- small asm helpers ------------------------------------------
__device__ __forceinline__ uint32_t smem_u32(const void* p) {
    uint32_t a;
    asm("{ .reg .u64 t; cvta.to.shared.u64 t, %1; cvt.u32.u64 %0, t; }" : "=r"(a) : "l"(p));
    return a;
}
__device__ __forceinline__ void cp_async16(uint32_t s, const void* g) {
    asm volatile("cp.async.cg.shared.global [%0], [%1], 16;" :: "r"(s), "l"(g));
}
#define CP_COMMIT() asm volatile("cp.async.commit_group;")
#define CP_WAIT(N)  asm volatile("cp.async.wait_group %0;" :: "n"(N))

__device__ __forceinline__ void ldsm_x4(uint32_t* r, uint32_t addr) {
    asm volatile("ldmatrix.sync.aligned.m8n8.x4.shared.b16 {%0,%1,%2,%3}, [%4];"
        : "=r"(r[0]), "=r"(r[1]), "=r"(r[2]), "=r"(r[3]) : "r"(addr));
}

__device__ __forceinline__ float tf32r(float x) {
    float y;
    asm("cvt.rna.tf32.f32 %0, %1;" : "=f"(y) : "f"(x));
    return y;
}
// tf32 mma with uint32 (raw-bit) fragments
__device__ __forceinline__ void mma_tf32u(float* d, const uint32_t* a, const uint32_t* b) {
    asm volatile(
        "mma.sync.aligned.m16n8k8.row.col.f32.tf32.tf32.f32 "
        "{%0,%1,%2,%3}, {%4,%5,%6,%7}, {%8,%9}, {%0,%1,%2,%3};"
        : "+f"(d[0]), "+f"(d[1]), "+f"(d[2]), "+f"(d[3])
        : "r"(a[0]), "r"(a[1]), "r"(a[2]), "r"(a[3]), "r"(b[0]), "r"(b[1]));
}

__device__ __forceinline__ float gelu_exact(float x) {
    return 0.5f * x * (1.0f + erff(x * 0.70710678118654752f));
}

// ---------------- tf32 mma.sync GEMM, 128x128 tile, 8 warps (2x4), BK=32 -----
// Warp tile 64x32. A: ldsm.x4 per (mt,ks). B: ldsm.x4 per (nt, ks-pair)
// (matrices = {ks.seg0, ks.seg1, ks+1.seg0, ks+1.seg1}; regs map directly).
#define GK    32
#define GSROW 36
#define GEMM_SMEM (2*(128+128)*GSROW*4)

__global__ __launch_bounds__(256, 2)
void gemm_tc(const float* __restrict__ A, const float* __restrict__ BT,
             const float* __restrict__ bias, float* __restrict__ Cf,
             int M, int N, int K, int act, int round_out)
{
    extern __shared__ __align__(16) float smf[];
    const int tid  = threadIdx.x;
    const int wid  = tid >> 5;
    const int lane = tid & 31;
    const int wm   = wid >> 2;    // 0..1  (64 rows each)
    const int wn   = wid & 3;     // 0..3  (32 cols each)
    const int row0 = blockIdx.y * 128;
    const int col0 = blockIdx.x * 128;

    float* Asf[2] = { smf,              smf + 256*GSROW };
    float* Bsf[2] = { smf + 128*GSROW,  smf + 256*GSROW + 128*GSROW };
    const uint32_t sAu[2] = { smem_u32(Asf[0]), smem_u32(Asf[1]) };
    const uint32_t sBu[2] = { smem_u32(Bsf[0]), smem_u32(Bsf[1]) };

    const int m8 = lane >> 3;          // 0..3 (matrix index for x4)
    const int lr = lane & 7;           // row within matrix
    // A x4 per (mt, ks): matrices {r+0.seg0},{r+8.seg0},{r+0.seg1},{r+8.seg1}
    uint32_t aoff[4];
    #pragma unroll
    for (int mt = 0; mt < 4; mt++)
        aoff[mt] = (uint32_t)((wm*64 + mt*16 + (m8 & 1)*8 + lr) * GSROW) * 4 + (m8 >> 1) * 16;
    // B x4 per (nt, ks-pair): same rows in all groups; offsets select ks/seg
    uint32_t boff[4];
    #pragma unroll
    for (int nt = 0; nt < 4; nt++)
        boff[nt] = (uint32_t)((wn*32 + nt*8 + lr) * GSROW) * 4 + (m8 >> 1) * 32 + (m8 & 1) * 16;

    float acc[4][4][4];
    #pragma unroll
    for (int i = 0; i < 4; i++)
        #pragma unroll
        for (int j = 0; j < 4; j++)
            #pragma unroll
            for (int q = 0; q < 4; q++) acc[i][j][q] = 0.0f;

    const int nChunks = K / GK;

    auto load_chunk = [&](int c, int st) {
        const int k0 = c * GK;
        #pragma unroll
        for (int i = 0; i < 4; i++) {
            const int idx = i * 256 + tid;
            const int r = idx >> 3, j = idx & 7;
            cp_async16(sAu[st] + (uint32_t)(r * GSROW + j * 4) * 4,
                       A + (size_t)(row0 + r) * K + k0 + j * 4);
        }
        #pragma unroll
        for (int i = 0; i < 4; i++) {
            const int idx = i * 256 + tid;
            const int r = idx >> 3, j = idx & 7;
            cp_async16(sBu[st] + (uint32_t)(r * GSROW + j * 4) * 4,
                       BT + (size_t)(col0 + r) * K + k0 + j * 4);
        }
        CP_COMMIT();
    };

    load_chunk(0, 0);

    for (int c = 0; c < nChunks; c++) {
        const int st = c & 1;
        if (c + 1 < nChunks) { load_chunk(c + 1, st ^ 1); CP_WAIT(1); }
        else                 { CP_WAIT(0); }
        __syncthreads();

        const uint32_t sa = sAu[st];
        const uint32_t sb = sBu[st];

        #pragma unroll
        for (int ks2 = 0; ks2 < 2; ks2++) {
            uint32_t bks[4][4];
            #pragma unroll
            for (int nt = 0; nt < 4; nt++)
                ldsm_x4(bks[nt], sb + boff[nt] + ks2 * 64);
            #pragma unroll
            for (int ksi = 0; ksi < 2; ksi++) {
                uint32_t af[4][4];
                #pragma unroll
                for (int mt = 0; mt < 4; mt++)
                    ldsm_x4(af[mt], sa + aoff[mt] + ks2 * 64 + ksi * 32);
                #pragma unroll
                for (int mt = 0; mt < 4; mt++)
                    #pragma unroll
                    for (int nt = 0; nt < 4; nt++)
                        mma_tf32u(acc[mt][nt], af[mt], &bks[nt][ksi * 2]);
            }
        }
        __syncthreads();
    }

    // ---- epilogue ----
    const int gr = lane >> 2;
    const int gc = (lane & 3) * 2;
    #pragma unroll
    for (int mt = 0; mt < 4; mt++) {
        #pragma unroll
        for (int nt = 0; nt < 4; nt++) {
            const int rA = row0 + wm * 64 + mt * 16 + gr;
            const int cA = col0 + wn * 32 + nt * 8 + gc;
            float b0 = 0.f, b1 = 0.f;
            if (bias) { b0 = bias[cA]; b1 = bias[cA + 1]; }
            float v00 = acc[mt][nt][0] + b0, v01 = acc[mt][nt][1] + b1;
            float v10 = acc[mt][nt][2] + b0, v11 = acc[mt][nt][3] + b1;
            if (act == 1) {
                v00 = gelu_exact(v00); v01 = gelu_exact(v01);
                v10 = gelu_exact(v10); v11 = gelu_exact(v11);
            }
            if (round_out) {
                v00 = tf32r(v00); v01 = tf32r(v01);
                v10 = tf32r(v10); v11 = tf32r(v11);
            }
            *(float2*)&Cf[(size_t)rA * N + cA]       = make_float2(v00, v01);
            *(float2*)&Cf[(size_t)(rA + 8) * N + cA] = make_float2(v10, v11);
        }
    }
}

// ---------------- fp32 -> tf32-rounded fp32 ----------------------------------
__global__ void round_tf32(const float* __restrict__ in, float* __restrict__ out, int n)
{
    const int i = (blockIdx.x * blockDim.x + threadIdx.x) * 4;
    if (i < n) {
        float4 v = *(const float4*)(in + i);
        v.x = tf32r(v.x); v.y = tf32r(v.y); v.z = tf32r(v.z); v.w = tf32r(v.w);
        *(float4*)(out + i) = v;
    }
}

// ---------------- all weight transposes in one launch -------------------------
__global__ void transpose_all(const float* __restrict__ wq, const float* __restrict__ wk,
                              const float* __restrict__ wv, const float* __restrict__ wo,
                              const float* __restrict__ w1, const float* __restrict__ w2,
                              float* __restrict__ WTqkv, float* __restrict__ WTo,
                              float* __restrict__ WT1, float* __restrict__ WT2)
{
    const int idx = blockIdx.x;
    const float* W; float* WT; int Nd, Kd, bx, by;
    if (idx < 3072) {
        const int w = idx >> 10, t = idx & 1023;
        W  = (w == 0) ? wq : (w == 1) ? wk : wv;
        WT = WTqkv + (size_t)w * D_MODEL * D_MODEL;
        Nd = D_MODEL; Kd = D_MODEL; bx = (t & 31) * 32; by = (t >> 5) * 32;
    } else if (idx < 4096) {
        const int t = idx - 3072;
        W = wo; WT = WTo;
        Nd = D_MODEL; Kd = D_MODEL; bx = (t & 31) * 32; by = (t >> 5) * 32;
    } else if (idx < 8192) {
        const int t = idx - 4096;
        W = w1; WT = WT1;
        Nd = DHID; Kd = D_MODEL; bx = (t & 127) * 32; by = (t >> 7) * 32;
    } else {
        const int t = idx - 8192;
        W = w2; WT = WT2;
        Nd = D_MODEL; Kd = DHID; bx = (t & 31) * 32; by = (t >> 5) * 32;
    }

    __shared__ float tbuf[32][33];
    const int tx = threadIdx.x, ty = threadIdx.y;
    #pragma unroll
    for (int i = ty; i < 32; i += 8)
        tbuf[i][tx] = W[(size_t)(by + i) * Nd + bx + tx];
    __syncthreads();
    #pragma unroll
    for (int i = ty; i < 32; i += 8)
        WT[(size_t)(bx + i) * Kd + by + tx] = tf32r(tbuf[tx][i]);
}

// ---------------- bias concat -------------------------------------------------
__global__ void concat_bias(const float* __restrict__ bq, const float* __restrict__ bk,
                            const float* __restrict__ bv, float* __restrict__ o)
{
    const int i = blockIdx.x * 256 + threadIdx.x;
    if (i < 1024)       o[i] = bq[i];
    else if (i < 2048)  o[i] = bk[i - 1024];
    else if (i < 3072)  o[i] = bv[i - 2048];
}

// ---------------- tensor-core flash attention (tf32) -------------------------
// 64-row Q tile, 128 thr, cp.async double-buffered KV, K frags via ks-fused x4.
#define KPAD 68
#define VPAD 72
#define ATTN_SMEM ((2*(64*KPAD + 64*VPAD) + 64*KPAD) * 4)

__global__ __launch_bounds__(128)
void attn_tc(const float* __restrict__ Qp, const float* __restrict__ Kp,
             const float* __restrict__ Vp, float* __restrict__ O,
             int ldq, int ldo)
{
    extern __shared__ float sm[];
    float* Kbuf[2] = { sm,               sm + 64*KPAD };
    float* Vbuf[2] = { sm + 2*64*KPAD,   sm + 2*64*KPAD + 64*VPAD };
    float* Ps      = sm + 2*64*KPAD + 2*64*VPAD;
    const uint32_t ku[2] = { smem_u32(Kbuf[0]), smem_u32(Kbuf[1]) };
    const uint32_t vu[2] = { smem_u32(Vbuf[0]), smem_u32(Vbuf[1]) };
    const uint32_t psu = smem_u32(Ps);

    const int qt   = (int)gridDim.x - 1 - (int)blockIdx.x;   // long blocks first
    const int bh   = blockIdx.y;
    const int b    = bh >> 4;
    const int h    = bh & 15;
    const int tid  = threadIdx.x;
    const int wid  = tid >> 5;
    const int lane = tid & 31;
    const int r0   = lane >> 2;
    const int c0   = lane & 3;
    const int m8   = lane >> 3;
    const int lr   = lane & 7;
    const int prow = wid * 16;

    // K x4 per (nt, ks-pair): rows nt*8+lr; groups select {ks.seg0, ks.seg1, ks+1.seg0, ks+1.seg1}
    uint32_t koff[8];
    #pragma unroll
    for (int nt = 0; nt < 8; nt++)
        koff[nt] = (uint32_t)((nt*8 + lr) * KPAD) * 4 + (m8 >> 1) * 32 + (m8 & 1) * 16;
    const uint32_t poff = (uint32_t)((prow + (m8 & 1)*8 + lr) * KPAD) * 4 + (m8 >> 1) * 16;

    uint32_t qa[8][4];
    {
        const size_t qbase = ((size_t)(b * SEQ + qt * 64 + wid * 16)) * ldq + h * 64;
        #pragma unroll
        for (int ks = 0; ks < 8; ks++) {
            qa[ks][0] = __float_as_uint(Qp[qbase + (size_t)r0 * ldq + ks * 8 + c0] * 0.125f);
            qa[ks][1] = __float_as_uint(Qp[qbase + (size_t)(r0 + 8) * ldq + ks * 8 + c0] * 0.125f);
            qa[ks][2] = __float_as_uint(Qp[qbase + (size_t)r0 * ldq + ks * 8 + c0 + 4] * 0.125f);
            qa[ks][3] = __float_as_uint(Qp[qbase + (size_t)(r0 + 8) * ldq + ks * 8 + c0 + 4] * 0.125f);
        }
    }

    float o[8][4];
    #pragma unroll
    for (int nt = 0; nt < 8; nt++)
        #pragma unroll
        for (int q = 0; q < 4; q++) o[nt][q] = 0.0f;
    float mA = -1e30f, mB = -1e30f, lA = 0.0f, lB = 0.0f;

    const size_t kvbase = ((size_t)b * SEQ) * ldq + h * 64;

    auto load_kv = [&](int kt, int st) {
        #pragma unroll
        for (int i = 0; i < 8; i++) {
            const int idx = i * 128 + tid;
            const int r   = idx >> 4;
            const int c4  = (idx & 15) << 2;
            const size_t src = kvbase + (size_t)(kt * 64 + r) * ldq + c4;
            cp_async16(ku[st] + (uint32_t)(r * KPAD + c4) * 4, Kp + src);
            cp_async16(vu[st] + (uint32_t)(r * VPAD + c4) * 4, Vp + src);
        }
        CP_COMMIT();
    };

    const int nkt = qt + 1;
    load_kv(0, 0);

    for (int kt = 0; kt < nkt; kt++) {
        const int st = kt & 1;
        if (kt + 1 < nkt) { load_kv(kt + 1, st ^ 1); CP_WAIT(1); }
        else              { CP_WAIT(0); }
        __syncthreads();

        const uint32_t ksu = ku[st];
        const float*   Vs  = Vbuf[st];

        float s[8][4];
        #pragma unroll
        for (int nt = 0; nt < 8; nt++)
            #pragma unroll
            for (int q = 0; q < 4; q++) s[nt][q] = 0.0f;

        #pragma unroll
        for (int ks2 = 0; ks2 < 4; ks2++) {
            #pragma unroll
            for (int nt = 0; nt < 8; nt++) {
                uint32_t r[4];
                ldsm_x4(r, ksu + koff[nt] + ks2 * 64);
                mma_tf32u(s[nt], qa[2*ks2],     r);
                mma_tf32u(s[nt], qa[2*ks2 + 1], r + 2);
            }
        }

        if (kt == qt) {
            const int rA = wid * 16 + r0;
            const int rB = rA + 8;
            #pragma unroll
            for (int nt = 0; nt < 8; nt++) {
                const int cc = nt * 8 + c0 * 2;
                if (cc     > rA) s[nt][0] = -1e30f;
                if (cc + 1 > rA) s[nt][1] = -1e30f;
                if (cc     > rB) s[nt][2] = -1e30f;
                if (cc + 1 > rB) s[nt][3] = -1e30f;
            }
        }

        float tmA = -1e30f, tmB = -1e30f;
        #pragma unroll
        for (int nt = 0; nt < 8; nt++) {
            tmA = fmaxf(tmA, fmaxf(s[nt][0], s[nt][1]));
            tmB = fmaxf(tmB, fmaxf(s[nt][2], s[nt][3]));
        }
        tmA = fmaxf(tmA, __shfl_xor_sync(0xffffffffu, tmA, 1));
        tmA = fmaxf(tmA, __shfl_xor_sync(0xffffffffu, tmA, 2));
        tmB = fmaxf(tmB, __shfl_xor_sync(0xffffffffu, tmB, 1));
        tmB = fmaxf(tmB, __shfl_xor_sync(0xffffffffu, tmB, 2));

        const float mnA = fmaxf(mA, tmA);
        const float mnB = fmaxf(mB, tmB);
        const float cA = __expf(mA - mnA);
        const float cB = __expf(mB - mnB);
        lA *= cA; lB *= cB;
        #pragma unroll
        for (int nt = 0; nt < 8; nt++) {
            o[nt][0] *= cA; o[nt][1] *= cA;
            o[nt][2] *= cB; o[nt][3] *= cB;
        }

        float sumA = 0.0f, sumB = 0.0f;
        #pragma unroll
        for (int nt = 0; nt < 8; nt++) {
            const float p0 = __expf(s[nt][0] - mnA);
            const float p1 = __expf(s[nt][1] - mnA);
            const float p2 = __expf(s[nt][2] - mnB);
            const float p3 = __expf(s[nt][3] - mnB);
            sumA += p0 + p1;
            sumB += p2 + p3;
            *(float2*)&Ps[(prow + r0) * KPAD + nt * 8 + c0 * 2]     = make_float2(tf32r(p0), tf32r(p1));
            *(float2*)&Ps[(prow + r0 + 8) * KPAD + nt * 8 + c0 * 2] = make_float2(tf32r(p2), tf32r(p3));
        }
        sumA += __shfl_xor_sync(0xffffffffu, sumA, 1);
        sumA += __shfl_xor_sync(0xffffffffu, sumA, 2);
        sumB += __shfl_xor_sync(0xffffffffu, sumB, 1);
        sumB += __shfl_xor_sync(0xffffffffu, sumB, 2);
        lA += sumA; lB += sumB;
        mA = mnA; mB = mnB;

        __syncwarp();

        #pragma unroll
        for (int ks = 0; ks < 8; ks++) {
            uint32_t af[4];
            ldsm_x4(af, psu + poff + ks * 32);
            #pragma unroll
            for (int nt = 0; nt < 8; nt++) {
                uint32_t bfr[2];
                bfr[0] = __float_as_uint(Vs[(ks * 8 + c0) * VPAD + nt * 8 + r0]);
                bfr[1] = __float_as_uint(Vs[(ks * 8 + c0 + 4) * VPAD + nt * 8 + r0]);
                mma_tf32u(o[nt], af, bfr);
            }
        }
        __syncthreads();
    }

    const float invA = 1.0f / lA;
    const float invB = 1.0f / lB;
    const size_t obase = ((size_t)(b * SEQ + qt * 64 + wid * 16)) * ldo + h * 64;
    #pragma unroll
    for (int nt = 0; nt < 8; nt++) {
        const int cc = nt * 8 + c0 * 2;
        *(float2*)&O[obase + (size_t)r0 * ldo + cc] =
            make_float2(tf32r(o[nt][0] * invA), tf32r(o[nt][1] * invA));
        *(float2*)&O[obase + (size_t)(r0 + 8) * ldo + cc] =
            make_float2(tf32r(o[nt][2] * invB), tf32r(o[nt][3] * invB));
    }
}

// ---------------- fused LayerNorm + residual add -----------------------------
__global__ void ln_res_kernel(const float* __restrict__ inp, const float* __restrict__ resid,
                              const float* __restrict__ gam, const float* __restrict__ bet,
                              float* __restrict__ out, float* __restrict__ out_r)
{
    const int row = blockIdx.x;
    const int tid = threadIdx.x;
    const float* v = inp + (size_t)row * D_MODEL;

    float vals[4];
    float s = 0.0f;
    #pragma unroll
    for (int i = 0; i < 4; i++) { vals[i] = v[tid + 256 * i]; s += vals[i]; }

    __shared__ float red1[8];
    __shared__ float red2[8];
    const int lane = tid & 31, w = tid >> 5;

    #pragma unroll
    for (int o = 16; o > 0; o >>= 1) s += __shfl_xor_sync(0xffffffffu, s, o);
    if (lane == 0) red1[w] = s;
    __syncthreads();
    float mu = 0.0f;
    #pragma unroll
    for (int i = 0; i < 8; i++) mu += red1[i];
    mu *= (1.0f / D_MODEL);

    float vs = 0.0f;
    #pragma unroll
    for (int i = 0; i < 4; i++) { float d = vals[i] - mu; vs += d * d; }
    #pragma unroll
    for (int o = 16; o > 0; o >>= 1) vs += __shfl_xor_sync(0xffffffffu, vs, o);
    if (lane == 0) red2[w] = vs;
    __syncthreads();
    float var = 0.0f;
    #pragma unroll
    for (int i = 0; i < 8; i++) var += red2[i];
    var *= (1.0f / D_MODEL);
    const float rs = rsqrtf(var + LN_EPS);

    #pragma unroll
    for (int i = 0; i < 4; i++) {
        const int idx = tid + 256 * i;
        const size_t off = (size_t)row * D_MODEL + idx;
        const float o = resid[off] + (vals[i] - mu) * rs * gam[idx] + bet[idx];
        out[off] = o;
        if (out_r) out_r[off] = tf32r(o);
    }
}

// ---------------- launch -----------------------------------------------------
extern "C" void kernel_launch(void* const* d_in, const int* in_sizes, int n_in,
                              void* d_out, int out_size)
{
    const float* x     = (const float*)d_in[0];
    const float* wq    = (const float*)d_in[1];
    const float* bq    = (const float*)d_in[2];
    const float* wk    = (const float*)d_in[3];
    const float* bk    = (const float*)d_in[4];
    const float* wv    = (const float*)d_in[5];
    const float* bv    = (const float*)d_in[6];
    const float* wo    = (const float*)d_in[7];
    const float* ln1_g = (const float*)d_in[8];
    const float* ln1_b = (const float*)d_in[9];
    const float* w1    = (const float*)d_in[10];
    const float* b1    = (const float*)d_in[11];
    const float* w2    = (const float*)d_in[12];
    const float* ln2_g = (const float*)d_in[13];
    const float* ln2_b = (const float*)d_in[14];
    float* out = (float*)d_out;

    void *pQKV, *pCTX, *pPRJ, *pX1, *pX1r, *pT, *pXr, *pH;
    void *pWTqkv, *pWTo, *pWT1, *pWT2, *pBqkv;
    cudaGetSymbolAddress(&pQKV,  g_QKV);
    cudaGetSymbolAddress(&pCTX,  g_CTX);
    cudaGetSymbolAddress(&pPRJ,  g_PRJ);
    cudaGetSymbolAddress(&pX1,   g_X1);
    cudaGetSymbolAddress(&pX1r,  g_X1r);
    cudaGetSymbolAddress(&pT,    g_T);
    cudaGetSymbolAddress(&pXr,   g_Xr);
    cudaGetSymbolAddress(&pH,    g_H);
    cudaGetSymbolAddress(&pWTqkv,g_WTqkv);
    cudaGetSymbolAddress(&pWTo,  g_WTo);
    cudaGetSymbolAddress(&pWT1,  g_WT1);
    cudaGetSymbolAddress(&pWT2,  g_WT2);
    cudaGetSymbolAddress(&pBqkv, g_Bqkv);
    float* QKV  = (float*)pQKV;  float* CTX = (float*)pCTX; float* PRJ = (float*)pPRJ;
    float* X1   = (float*)pX1;   float* X1r = (float*)pX1r; float* T   = (float*)pT;
    float* Xr   = (float*)pXr;   float* H   = (float*)pH;
    float* WTqkv= (float*)pWTqkv;float* WTo = (float*)pWTo;
    float* WT1  = (float*)pWT1;  float* WT2 = (float*)pWT2; float* Bqkv= (float*)pBqkv;

    cudaFuncSetAttribute(attn_tc, cudaFuncAttributeMaxDynamicSharedMemorySize, ATTN_SMEM);
    cudaFuncSetAttribute(gemm_tc, cudaFuncAttributeMaxDynamicSharedMemorySize, GEMM_SMEM);

    transpose_all<<<12288, dim3(32, 8)>>>(wq, wk, wv, wo, w1, w2, WTqkv, WTo, WT1, WT2);
    concat_bias<<<12, 256>>>(bq, bk, bv, Bqkv);

    const int nX = MROWS * D_MODEL;
    round_tf32<<<nX/1024, 256>>>(x, Xr, nX);

    const dim3 blk(256);
    // fused QKV projection: [4096,1024] @ [1024,3072] -> QKV (tf32-rounded)
    gemm_tc<<<dim3(3072/128, MROWS/128), blk, GEMM_SMEM>>>(Xr, WTqkv, Bqkv, QKV,
                                                           MROWS, 3072, D_MODEL, 0, 1);

    // tensor-core causal attention -> CTX [B,S,1024] (tf32-rounded)
    attn_tc<<<dim3(SEQ/64, BATCH*NHEADS), 128, ATTN_SMEM>>>(
        QKV, QKV + 1024, QKV + 2048, CTX, 3072, D_MODEL);

    // out projection + LN + residual
    gemm_tc<<<dim3(D_MODEL/128, MROWS/128), blk, GEMM_SMEM>>>(CTX, WTo, nullptr, PRJ,
                                                              MROWS, D_MODEL, D_MODEL, 0, 0);
    ln_res_kernel<<<MROWS, 256>>>(PRJ, x, ln1_g, ln1_b, X1, X1r);

    // FFN
    gemm_tc<<<dim3(DHID/128, MROWS/128), blk, GEMM_SMEM>>>(X1r, WT1, b1, H,
                                                           MROWS, DHID, D_MODEL, 1, 1);
    gemm_tc<<<dim3(D_MODEL/128, MROWS/128), blk, GEMM_SMEM>>>(H, WT2, nullptr, T,
                                                              MROWS, D_MODEL, DHID, 0, 0);
    ln_res_kernel<<<MROWS, 256>>>(T, X1, ln2_g, ln2_b, out, nullptr);
}

// round 16
// speedup vs baseline: 1.2010x; 1.2010x over previous
#include <cuda_runtime.h>
#include <cuda_fp16.h>
#include <math.h>
#include <cstdint>

#define D_MODEL 1024
#define DHEAD   64
#define NHEADS  16
#define DHID    4096
#define BATCH   2
#define SEQ     2048
#define MROWS   (BATCH*SEQ)   // 4096
#define LN_EPS  1e-5f

// ---------------- scratch (device globals; no allocations allowed) ----------
__device__ float  g_QKV [(size_t)MROWS*3072];
__device__ float  g_CTX [MROWS*D_MODEL];
__device__ float  g_PRJ [MROWS*D_MODEL];
__device__ float  g_X1  [MROWS*D_MODEL];
__device__ float  g_T   [MROWS*D_MODEL];
__device__ float  g_Xr  [MROWS*D_MODEL];
__device__ __half g_X1h [MROWS*D_MODEL];
__device__ __half g_Hh  [(size_t)MROWS*DHID];
__device__ float  g_WTqkv[(size_t)3*D_MODEL*D_MODEL];
__device__ float  g_WTo [D_MODEL*D_MODEL];
__device__ __half g_WT1h[(size_t)DHID*D_MODEL];
__device__ __half g_WT2h[(size_t)D_MODEL*DHID];
__device__ float  g_Bqkv[3072];

// ---------------- small asm helpers ------------------------------------------
__device__ __forceinline__ uint32_t smem_u32(const void* p) {
    uint32_t a;
    asm("{ .reg .u64 t; cvta.to.shared.u64 t, %1; cvt.u32.u64 %0, t; }" : "=r"(a) : "l"(p));
    return a;
}
__device__ __forceinline__ void cp_async16(uint32_t s, const void* g) {
    asm volatile("cp.async.cg.shared.global [%0], [%1], 16;" :: "r"(s), "l"(g));
}
#define CP_COMMIT() asm volatile("cp.async.commit_group;")
#define CP_WAIT(N)  asm volatile("cp.async.wait_group %0;" :: "n"(N))

__device__ __forceinline__ void ldsm_x4(uint32_t* r, uint32_t addr) {
    asm volatile("ldmatrix.sync.aligned.m8n8.x4.shared.b16 {%0,%1,%2,%3}, [%4];"
        : "=r"(r[0]), "=r"(r[1]), "=r"(r[2]), "=r"(r[3]) : "r"(addr));
}
__device__ __forceinline__ void ldsm_x2(uint32_t* r, uint32_t addr) {
    asm volatile("ldmatrix.sync.aligned.m8n8.x2.shared.b16 {%0,%1}, [%2];"
        : "=r"(r[0]), "=r"(r[1]) : "r"(addr));
}

__device__ __forceinline__ float tf32r(float x) {
    float y;
    asm("cvt.rna.tf32.f32 %0, %1;" : "=f"(y) : "f"(x));
    return y;
}
__device__ __forceinline__ void mma_tf32u(float* d, const uint32_t* a, const uint32_t* b) {
    asm volatile(
        "mma.sync.aligned.m16n8k8.row.col.f32.tf32.tf32.f32 "
        "{%0,%1,%2,%3}, {%4,%5,%6,%7}, {%8,%9}, {%0,%1,%2,%3};"
        : "+f"(d[0]), "+f"(d[1]), "+f"(d[2]), "+f"(d[3])
        : "r"(a[0]), "r"(a[1]), "r"(a[2]), "r"(a[3]), "r"(b[0]), "r"(b[1]));
}
__device__ __forceinline__ void mma_f16u(float* d, const uint32_t* a, const uint32_t* b) {
    asm volatile(
        "mma.sync.aligned.m16n8k16.row.col.f32.f16.f16.f32 "
        "{%0,%1,%2,%3}, {%4,%5,%6,%7}, {%8,%9}, {%0,%1,%2,%3};"
        : "+f"(d[0]), "+f"(d[1]), "+f"(d[2]), "+f"(d[3])
        : "r"(a[0]), "r"(a[1]), "r"(a[2]), "r"(a[3]), "r"(b[0]), "r"(b[1]));
}

__device__ __forceinline__ float gelu_exact(float x) {
    return 0.5f * x * (1.0f + erff(x * 0.70710678118654752f));
}

// ---------------- tf32 mma.sync GEMM (round-11 proven config) -----------------
#define GK    32
#define GSROW 36
#define GEMM_SMEM (2*(128+128)*GSROW*4)

__global__ __launch_bounds__(256, 2)
void gemm_tc(const float* __restrict__ A, const float* __restrict__ BT,
             const float* __restrict__ bias, float* __restrict__ Cf,
             int M, int N, int K, int round_out)
{
    extern __shared__ __align__(16) float smf[];
    const int tid  = threadIdx.x;
    const int wid  = tid >> 5;
    const int lane = tid & 31;
    const int wm   = wid >> 2;
    const int wn   = wid & 3;
    const int row0 = blockIdx.y * 128;
    const int col0 = blockIdx.x * 128;

    float* Asf[2] = { smf,              smf + 256*GSROW };
    float* Bsf[2] = { smf + 128*GSROW,  smf + 256*GSROW + 128*GSROW };
    const uint32_t sAu[2] = { smem_u32(Asf[0]), smem_u32(Asf[1]) };
    const uint32_t sBu[2] = { smem_u32(Bsf[0]), smem_u32(Bsf[1]) };

    const int m8 = lane >> 3;
    const int lr = lane & 7;
    uint32_t aoff[4];
    #pragma unroll
    for (int mt = 0; mt < 4; mt++)
        aoff[mt] = (uint32_t)((wm*64 + mt*16 + (m8 & 1)*8 + lr) * GSROW) * 4 + (m8 >> 1) * 16;
    uint32_t boff[4];
    #pragma unroll
    for (int nt = 0; nt < 4; nt++)
        boff[nt] = (uint32_t)((wn*32 + nt*8 + lr) * GSROW) * 4 + ((lane >> 3) & 1) * 16;

    float acc[4][4][4];
    #pragma unroll
    for (int i = 0; i < 4; i++)
        #pragma unroll
        for (int j = 0; j < 4; j++)
            #pragma unroll
            for (int q = 0; q < 4; q++) acc[i][j][q] = 0.0f;

    const int nChunks = K / GK;

    auto load_chunk = [&](int c, int st) {
        const int k0 = c * GK;
        #pragma unroll
        for (int i = 0; i < 4; i++) {
            const int idx = i * 256 + tid;
            const int r = idx >> 3, j = idx & 7;
            cp_async16(sAu[st] + (uint32_t)(r * GSROW + j * 4) * 4,
                       A + (size_t)(row0 + r) * K + k0 + j * 4);
        }
        #pragma unroll
        for (int i = 0; i < 4; i++) {
            const int idx = i * 256 + tid;
            const int r = idx >> 3, j = idx & 7;
            cp_async16(sBu[st] + (uint32_t)(r * GSROW + j * 4) * 4,
                       BT + (size_t)(col0 + r) * K + k0 + j * 4);
        }
        CP_COMMIT();
    };

    load_chunk(0, 0);

    for (int c = 0; c < nChunks; c++) {
        const int st = c & 1;
        if (c + 1 < nChunks) { load_chunk(c + 1, st ^ 1); CP_WAIT(1); }
        else                 { CP_WAIT(0); }
        __syncthreads();

        const uint32_t sa = sAu[st];
        const uint32_t sb = sBu[st];

        #pragma unroll
        for (int ks = 0; ks < 4; ks++) {
            uint32_t af[4][4], bfr[4][2];
            #pragma unroll
            for (int mt = 0; mt < 4; mt++)
                ldsm_x4(af[mt], sa + aoff[mt] + ks * 32);
            #pragma unroll
            for (int nt = 0; nt < 4; nt++)
                ldsm_x2(bfr[nt], sb + boff[nt] + ks * 32);
            #pragma unroll
            for (int mt = 0; mt < 4; mt++)
                #pragma unroll
                for (int nt = 0; nt < 4; nt++)
                    mma_tf32u(acc[mt][nt], af[mt], bfr[nt]);
        }
        __syncthreads();
    }

    const int gr = lane >> 2;
    const int gc = (lane & 3) * 2;
    #pragma unroll
    for (int mt = 0; mt < 4; mt++) {
        #pragma unroll
        for (int nt = 0; nt < 4; nt++) {
            const int rA = row0 + wm * 64 + mt * 16 + gr;
            const int cA = col0 + wn * 32 + nt * 8 + gc;
            float b0 = 0.f, b1 = 0.f;
            if (bias) { b0 = bias[cA]; b1 = bias[cA + 1]; }
            float v00 = acc[mt][nt][0] + b0, v01 = acc[mt][nt][1] + b1;
            float v10 = acc[mt][nt][2] + b0, v11 = acc[mt][nt][3] + b1;
            if (round_out) {
                v00 = tf32r(v00); v01 = tf32r(v01);
                v10 = tf32r(v10); v11 = tf32r(v11);
            }
            *(float2*)&Cf[(size_t)rA * N + cA]       = make_float2(v00, v01);
            *(float2*)&Cf[(size_t)(rA + 8) * N + cA] = make_float2(v10, v11);
        }
    }
}

// ---------------- fp16 mma.sync GEMM (m16n8k16, 2x MACs/instr) ----------------
// 128x128 tile, 8 warps (2x4), warp tile 64x32, BK=32 (2 k16 steps).
// Smem rows padded to 40 halves (80B): 16B-aligned, conflict-free ldsm.
#define HSROW 40

__global__ __launch_bounds__(256, 2)
void gemm_f16(const __half* __restrict__ A, const __half* __restrict__ BT,
              const float* __restrict__ bias, float* __restrict__ Cf,
              __half* __restrict__ Ch, int M, int N, int K, int act)
{
    __shared__ __align__(16) __half As[2][128 * HSROW];
    __shared__ __align__(16) __half Bs[2][128 * HSROW];

    const int tid  = threadIdx.x;
    const int wid  = tid >> 5;
    const int lane = tid & 31;
    const int wm   = wid >> 2;    // 0..1 (64 rows each)
    const int wn   = wid & 3;     // 0..3 (32 cols each)
    const int row0 = blockIdx.y * 128;
    const int col0 = blockIdx.x * 128;

    const uint32_t sAu[2] = { smem_u32(As[0]), smem_u32(As[1]) };
    const uint32_t sBu[2] = { smem_u32(Bs[0]), smem_u32(Bs[1]) };

    // ldmatrix lane addressing (round-3 verified layout)
    const int a_row = (lane & 7) + 8 * ((lane >> 3) & 1);
    const int a_k   = 8 * (lane >> 4);
    const int b_row = lane & 7;
    const int b_k   = 8 * ((lane >> 3) & 1);

    uint32_t aoff[4];
    #pragma unroll
    for (int mt = 0; mt < 4; mt++)
        aoff[mt] = (uint32_t)((wm*64 + mt*16 + a_row) * HSROW + a_k) * 2;
    uint32_t boff[4];
    #pragma unroll
    for (int nt = 0; nt < 4; nt++)
        boff[nt] = (uint32_t)((wn*32 + nt*8 + b_row) * HSROW + b_k) * 2;

    float acc[4][4][4];
    #pragma unroll
    for (int i = 0; i < 4; i++)
        #pragma unroll
        for (int j = 0; j < 4; j++)
            #pragma unroll
            for (int q = 0; q < 4; q++) acc[i][j][q] = 0.0f;

    const int nChunks = K / 32;

    // chunk: 128 rows x 32 halves each for A and B = 512 cp16 each
    auto load_chunk = [&](int c, int st) {
        const int k0 = c * 32;
        #pragma unroll
        for (int i = 0; i < 2; i++) {
            const int idx = i * 256 + tid;          // 0..511
            const int r = idx >> 2, j = (idx & 3) * 8;
            cp_async16(sAu[st] + (uint32_t)(r * HSROW + j) * 2,
                       A + (size_t)(row0 + r) * K + k0 + j);
        }
        #pragma unroll
        for (int i = 0; i < 2; i++) {
            const int idx = i * 256 + tid;
            const int r = idx >> 2, j = (idx & 3) * 8;
            cp_async16(sBu[st] + (uint32_t)(r * HSROW + j) * 2,
                       BT + (size_t)(col0 + r) * K + k0 + j);
        }
        CP_COMMIT();
    };

    load_chunk(0, 0);

    for (int c = 0; c < nChunks; c++) {
        const int st = c & 1;
        if (c + 1 < nChunks) { load_chunk(c + 1, st ^ 1); CP_WAIT(1); }
        else                 { CP_WAIT(0); }
        __syncthreads();

        const uint32_t sa = sAu[st];
        const uint32_t sb = sBu[st];

        #pragma unroll
        for (int ks = 0; ks < 2; ks++) {
            uint32_t af[4][4], bfr[4][2];
            #pragma unroll
            for (int mt = 0; mt < 4; mt++)
                ldsm_x4(af[mt], sa + aoff[mt] + ks * 32);   // +16 halves
            #pragma unroll
            for (int nt = 0; nt < 4; nt++)
                ldsm_x2(bfr[nt], sb + boff[nt] + ks * 32);
            #pragma unroll
            for (int mt = 0; mt < 4; mt++)
                #pragma unroll
                for (int nt = 0; nt < 4; nt++)
                    mma_f16u(acc[mt][nt], af[mt], bfr[nt]);
        }
        __syncthreads();
    }

    // ---- epilogue ----
    const int gr = lane >> 2;
    const int gc = (lane & 3) * 2;
    #pragma unroll
    for (int mt = 0; mt < 4; mt++) {
        #pragma unroll
        for (int nt = 0; nt < 4; nt++) {
            const int rA = row0 + wm * 64 + mt * 16 + gr;
            const int cA = col0 + wn * 32 + nt * 8 + gc;
            float b0 = 0.f, b1 = 0.f;
            if (bias) { b0 = bias[cA]; b1 = bias[cA + 1]; }
            float v00 = acc[mt][nt][0] + b0, v01 = acc[mt][nt][1] + b1;
            float v10 = acc[mt][nt][2] + b0, v11 = acc[mt][nt][3] + b1;
            if (act == 1) {
                v00 = gelu_exact(v00); v01 = gelu_exact(v01);
                v10 = gelu_exact(v10); v11 = gelu_exact(v11);
            }
            if (Cf) {
                *(float2*)&Cf[(size_t)rA * N + cA]       = make_float2(v00, v01);
                *(float2*)&Cf[(size_t)(rA + 8) * N + cA] = make_float2(v10, v11);
            }
            if (Ch) {
                *(__half2*)&Ch[(size_t)rA * N + cA]       = __floats2half2_rn(v00, v01);
                *(__half2*)&Ch[(size_t)(rA + 8) * N + cA] = __floats2half2_rn(v10, v11);
            }
        }
    }
}

// ---------------- fp32 -> tf32-rounded fp32 ----------------------------------
__global__ void round_tf32(const float* __restrict__ in, float* __restrict__ out, int n)
{
    const int i = (blockIdx.x * blockDim.x + threadIdx.x) * 4;
    if (i < n) {
        float4 v = *(const float4*)(in + i);
        v.x = tf32r(v.x); v.y = tf32r(v.y); v.z = tf32r(v.z); v.w = tf32r(v.w);
        *(float4*)(out + i) = v;
    }
}

// ---------------- weight transposes -------------------------------------------
// tf32 set: wq/wk/wv -> WTqkv [0,3072), wo -> WTo [3072,4096)
__global__ void transpose_f32(const float* __restrict__ wq, const float* __restrict__ wk,
                              const float* __restrict__ wv, const float* __restrict__ wo,
                              float* __restrict__ WTqkv, float* __restrict__ WTo)
{
    const int idx = blockIdx.x;
    const float* W; float* WT; int bx, by;
    if (idx < 3072) {
        const int w = idx >> 10, t = idx & 1023;
        W  = (w == 0) ? wq : (w == 1) ? wk : wv;
        WT = WTqkv + (size_t)w * D_MODEL * D_MODEL;
        bx = (t & 31) * 32; by = (t >> 5) * 32;
    } else {
        const int t = idx - 3072;
        W = wo; WT = WTo;
        bx = (t & 31) * 32; by = (t >> 5) * 32;
    }
    __shared__ float tbuf[32][33];
    const int tx = threadIdx.x, ty = threadIdx.y;
    #pragma unroll
    for (int i = ty; i < 32; i += 8)
        tbuf[i][tx] = W[(size_t)(by + i) * D_MODEL + bx + tx];
    __syncthreads();
    #pragma unroll
    for (int i = ty; i < 32; i += 8)
        WT[(size_t)(bx + i) * D_MODEL + by + tx] = tf32r(tbuf[tx][i]);
}

// fp16 set: w1 [0,4096), w2 [4096,8192)
__global__ void transpose_f16(const float* __restrict__ w1, const float* __restrict__ w2,
                              __half* __restrict__ WT1h, __half* __restrict__ WT2h)
{
    const int idx = blockIdx.x;
    const float* W; __half* WT; int Nd, Kd, bx, by;
    if (idx < 4096) {
        W = w1; WT = WT1h;
        Nd = DHID; Kd = D_MODEL;
        bx = (idx & 127) * 32; by = (idx >> 7) * 32;
    } else {
        const int t = idx - 4096;
        W = w2; WT = WT2h;
        Nd = D_MODEL; Kd = DHID;
        bx = (t & 31) * 32; by = (t >> 5) * 32;
    }
    __shared__ float tbuf[32][33];
    const int tx = threadIdx.x, ty = threadIdx.y;
    #pragma unroll
    for (int i = ty; i < 32; i += 8)
        tbuf[i][tx] = W[(size_t)(by + i) * Nd + bx + tx];
    __syncthreads();
    #pragma unroll
    for (int i = ty; i < 32; i += 8)
        WT[(size_t)(bx + i) * Kd + by + tx] = __float2half_rn(tbuf[tx][i]);
}

// ---------------- bias concat -------------------------------------------------
__global__ void concat_bias(const float* __restrict__ bq, const float* __restrict__ bk,
                            const float* __restrict__ bv, float* __restrict__ o)
{
    const int i = blockIdx.x * 256 + threadIdx.x;
    if (i < 1024)       o[i] = bq[i];
    else if (i < 2048)  o[i] = bk[i - 1024];
    else if (i < 3072)  o[i] = bv[i - 2048];
}

// ---------------- tensor-core flash attention (tf32, round-11 exact) ----------
#define KPAD 68
#define VPAD 72
#define ATTN_SMEM ((64*KPAD + 64*VPAD + 64*KPAD) * 4)

__global__ __launch_bounds__(128)
void attn_tc(const float* __restrict__ Qp, const float* __restrict__ Kp,
             const float* __restrict__ Vp, float* __restrict__ O,
             int ldq, int ldo)
{
    extern __shared__ float sm[];
    float* Ks = sm;
    float* Vs = sm + 64 * KPAD;
    float* Ps = sm + 64 * KPAD + 64 * VPAD;
    const uint32_t ksu = smem_u32(Ks);
    const uint32_t psu = smem_u32(Ps);

    const int qt   = (int)gridDim.x - 1 - (int)blockIdx.x;
    const int bh   = blockIdx.y;
    const int b    = bh >> 4;
    const int h    = bh & 15;
    const int tid  = threadIdx.x;
    const int wid  = tid >> 5;
    const int lane = tid & 31;
    const int r0   = lane >> 2;
    const int c0   = lane & 3;
    const int m8   = lane >> 3;
    const int lr   = lane & 7;
    const int prow = wid * 16;

    uint32_t koff[8];
    #pragma unroll
    for (int nt = 0; nt < 8; nt++)
        koff[nt] = (uint32_t)((nt*8 + lr) * KPAD) * 4 + ((lane >> 3) & 1) * 16;
    const uint32_t poff = (uint32_t)((prow + (m8 & 1)*8 + lr) * KPAD) * 4 + (m8 >> 1) * 16;

    uint32_t qa[8][4];
    {
        const size_t qbase = ((size_t)(b * SEQ + qt * 64 + wid * 16)) * ldq + h * 64;
        #pragma unroll
        for (int ks = 0; ks < 8; ks++) {
            qa[ks][0] = __float_as_uint(Qp[qbase + (size_t)r0 * ldq + ks * 8 + c0] * 0.125f);
            qa[ks][1] = __float_as_uint(Qp[qbase + (size_t)(r0 + 8) * ldq + ks * 8 + c0] * 0.125f);
            qa[ks][2] = __float_as_uint(Qp[qbase + (size_t)r0 * ldq + ks * 8 + c0 + 4] * 0.125f);
            qa[ks][3] = __float_as_uint(Qp[qbase + (size_t)(r0 + 8) * ldq + ks * 8 + c0 + 4] * 0.125f);
        }
    }

    float o[8][4];
    #pragma unroll
    for (int nt = 0; nt < 8; nt++)
        #pragma unroll
        for (int q = 0; q < 4; q++) o[nt][q] = 0.0f;
    float mA = -1e30f, mB = -1e30f, lA = 0.0f, lB = 0.0f;

    const size_t kvbase = ((size_t)b * SEQ) * ldq + h * 64;

    for (int kt = 0; kt <= qt; kt++) {
        #pragma unroll
        for (int i = 0; i < 8; i++) {
            const int idx = i * 128 + tid;
            const int r   = idx >> 4;
            const int c4  = (idx & 15) << 2;
            const size_t src = kvbase + (size_t)(kt * 64 + r) * ldq + c4;
            *(float4*)&Ks[r * KPAD + c4] = *(const float4*)(Kp + src);
            *(float4*)&Vs[r * VPAD + c4] = *(const float4*)(Vp + src);
        }
        __syncthreads();

        float s[8][4];
        #pragma unroll
        for (int nt = 0; nt < 8; nt++)
            #pragma unroll
            for (int q = 0; q < 4; q++) s[nt][q] = 0.0f;

        #pragma unroll
        for (int ks = 0; ks < 8; ks++) {
            #pragma unroll
            for (int nt = 0; nt < 8; nt++) {
                uint32_t bfr[2];
                ldsm_x2(bfr, ksu + koff[nt] + ks * 32);
                mma_tf32u(s[nt], qa[ks], bfr);
            }
        }

        if (kt == qt) {
            const int rA = wid * 16 + r0;
            const int rB = rA + 8;
            #pragma unroll
            for (int nt = 0; nt < 8; nt++) {
                const int cc = nt * 8 + c0 * 2;
                if (cc     > rA) s[nt][0] = -1e30f;
                if (cc + 1 > rA) s[nt][1] = -1e30f;
                if (cc     > rB) s[nt][2] = -1e30f;
                if (cc + 1 > rB) s[nt][3] = -1e30f;
            }
        }

        float tmA = -1e30f, tmB = -1e30f;
        #pragma unroll
        for (int nt = 0; nt < 8; nt++) {
            tmA = fmaxf(tmA, fmaxf(s[nt][0], s[nt][1]));
            tmB = fmaxf(tmB, fmaxf(s[nt][2], s[nt][3]));
        }
        tmA = fmaxf(tmA, __shfl_xor_sync(0xffffffffu, tmA, 1));
        tmA = fmaxf(tmA, __shfl_xor_sync(0xffffffffu, tmA, 2));
        tmB = fmaxf(tmB, __shfl_xor_sync(0xffffffffu, tmB, 1));
        tmB = fmaxf(tmB, __shfl_xor_sync(0xffffffffu, tmB, 2));

        const float mnA = fmaxf(mA, tmA);
        const float mnB = fmaxf(mB, tmB);
        const float cA = __expf(mA - mnA);
        const float cB = __expf(mB - mnB);
        lA *= cA; lB *= cB;
        #pragma unroll
        for (int nt = 0; nt < 8; nt++) {
            o[nt][0] *= cA; o[nt][1] *= cA;
            o[nt][2] *= cB; o[nt][3] *= cB;
        }

        float sumA = 0.0f, sumB = 0.0f;
        #pragma unroll
        for (int nt = 0; nt < 8; nt++) {
            const float p0 = __expf(s[nt][0] - mnA);
            const float p1 = __expf(s[nt][1] - mnA);
            const float p2 = __expf(s[nt][2] - mnB);
            const float p3 = __expf(s[nt][3] - mnB);
            sumA += p0 + p1;
            sumB += p2 + p3;
            *(float2*)&Ps[(prow + r0) * KPAD + nt * 8 + c0 * 2]     = make_float2(tf32r(p0), tf32r(p1));
            *(float2*)&Ps[(prow + r0 + 8) * KPAD + nt * 8 + c0 * 2] = make_float2(tf32r(p2), tf32r(p3));
        }
        sumA += __shfl_xor_sync(0xffffffffu, sumA, 1);
        sumA += __shfl_xor_sync(0xffffffffu, sumA, 2);
        sumB += __shfl_xor_sync(0xffffffffu, sumB, 1);
        sumB += __shfl_xor_sync(0xffffffffu, sumB, 2);
        lA += sumA; lB += sumB;
        mA = mnA; mB = mnB;

        __syncwarp();

        #pragma unroll
        for (int ks = 0; ks < 8; ks++) {
            uint32_t af[4];
            ldsm_x4(af, psu + poff + ks * 32);
            #pragma unroll
            for (int nt = 0; nt < 8; nt++) {
                uint32_t bfr[2];
                bfr[0] = __float_as_uint(Vs[(ks * 8 + c0) * VPAD + nt * 8 + r0]);
                bfr[1] = __float_as_uint(Vs[(ks * 8 + c0 + 4) * VPAD + nt * 8 + r0]);
                mma_tf32u(o[nt], af, bfr);
            }
        }
        __syncthreads();
    }

    const float invA = 1.0f / lA;
    const float invB = 1.0f / lB;
    const size_t obase = ((size_t)(b * SEQ + qt * 64 + wid * 16)) * ldo + h * 64;
    #pragma unroll
    for (int nt = 0; nt < 8; nt++) {
        const int cc = nt * 8 + c0 * 2;
        *(float2*)&O[obase + (size_t)r0 * ldo + cc] =
            make_float2(tf32r(o[nt][0] * invA), tf32r(o[nt][1] * invA));
        *(float2*)&O[obase + (size_t)(r0 + 8) * ldo + cc] =
            make_float2(tf32r(o[nt][2] * invB), tf32r(o[nt][3] * invB));
    }
}

// ---------------- fused LayerNorm + residual add -----------------------------
// out = resid + LN(inp)*g + b (fp32).  out_h (optional) = fp16 copy.
__global__ void ln_res_kernel(const float* __restrict__ inp, const float* __restrict__ resid,
                              const float* __restrict__ gam, const float* __restrict__ bet,
                              float* __restrict__ out, __half* __restrict__ out_h)
{
    const int row = blockIdx.x;
    const int tid = threadIdx.x;
    const float* v = inp + (size_t)row * D_MODEL;

    float vals[4];
    float s = 0.0f;
    #pragma unroll
    for (int i = 0; i < 4; i++) { vals[i] = v[tid + 256 * i]; s += vals[i]; }

    __shared__ float red1[8];
    __shared__ float red2[8];
    const int lane = tid & 31, w = tid >> 5;

    #pragma unroll
    for (int o = 16; o > 0; o >>= 1) s += __shfl_xor_sync(0xffffffffu, s, o);
    if (lane == 0) red1[w] = s;
    __syncthreads();
    float mu = 0.0f;
    #pragma unroll
    for (int i = 0; i < 8; i++) mu += red1[i];
    mu *= (1.0f / D_MODEL);

    float vs = 0.0f;
    #pragma unroll
    for (int i = 0; i < 4; i++) { float d = vals[i] - mu; vs += d * d; }
    #pragma unroll
    for (int o = 16; o > 0; o >>= 1) vs += __shfl_xor_sync(0xffffffffu, vs, o);
    if (lane == 0) red2[w] = vs;
    __syncthreads();
    float var = 0.0f;
    #pragma unroll
    for (int i = 0; i < 8; i++) var += red2[i];
    var *= (1.0f / D_MODEL);
    const float rs = rsqrtf(var + LN_EPS);

    #pragma unroll
    for (int i = 0; i < 4; i++) {
        const int idx = tid + 256 * i;
        const size_t off = (size_t)row * D_MODEL + idx;
        const float o = resid[off] + (vals[i] - mu) * rs * gam[idx] + bet[idx];
        out[off] = o;
        if (out_h) out_h[off] = __float2half_rn(o);
    }
}

// ---------------- launch -----------------------------------------------------
extern "C" void kernel_launch(void* const* d_in, const int* in_sizes, int n_in,
                              void* d_out, int out_size)
{
    const float* x     = (const float*)d_in[0];
    const float* wq    = (const float*)d_in[1];
    const float* bq    = (const float*)d_in[2];
    const float* wk    = (const float*)d_in[3];
    const float* bk    = (const float*)d_in[4];
    const float* wv    = (const float*)d_in[5];
    const float* bv    = (const float*)d_in[6];
    const float* wo    = (const float*)d_in[7];
    const float* ln1_g = (const float*)d_in[8];
    const float* ln1_b = (const float*)d_in[9];
    const float* w1    = (const float*)d_in[10];
    const float* b1    = (const float*)d_in[11];
    const float* w2    = (const float*)d_in[12];
    const float* ln2_g = (const float*)d_in[13];
    const float* ln2_b = (const float*)d_in[14];
    float* out = (float*)d_out;

    void *pQKV, *pCTX, *pPRJ, *pX1, *pT, *pXr, *pX1h, *pHh;
    void *pWTqkv, *pWTo, *pWT1h, *pWT2h, *pBqkv;
    cudaGetSymbolAddress(&pQKV,  g_QKV);
    cudaGetSymbolAddress(&pCTX,  g_CTX);
    cudaGetSymbolAddress(&pPRJ,  g_PRJ);
    cudaGetSymbolAddress(&pX1,   g_X1);
    cudaGetSymbolAddress(&pT,    g_T);
    cudaGetSymbolAddress(&pXr,   g_Xr);
    cudaGetSymbolAddress(&pX1h,  g_X1h);
    cudaGetSymbolAddress(&pHh,   g_Hh);
    cudaGetSymbolAddress(&pWTqkv,g_WTqkv);
    cudaGetSymbolAddress(&pWTo,  g_WTo);
    cudaGetSymbolAddress(&pWT1h, g_WT1h);
    cudaGetSymbolAddress(&pWT2h, g_WT2h);
    cudaGetSymbolAddress(&pBqkv, g_Bqkv);
    float*  QKV  = (float*)pQKV;   float* CTX = (float*)pCTX;  float* PRJ = (float*)pPRJ;
    float*  X1   = (float*)pX1;    float* T   = (float*)pT;    float* Xr  = (float*)pXr;
    __half* X1h  = (__half*)pX1h;  __half* Hh = (__half*)pHh;
    float*  WTqkv= (float*)pWTqkv; float* WTo = (float*)pWTo;
    __half* WT1h = (__half*)pWT1h; __half* WT2h = (__half*)pWT2h;
    float*  Bqkv = (float*)pBqkv;

    cudaFuncSetAttribute(attn_tc, cudaFuncAttributeMaxDynamicSharedMemorySize, ATTN_SMEM);
    cudaFuncSetAttribute(gemm_tc, cudaFuncAttributeMaxDynamicSharedMemorySize, GEMM_SMEM);

    transpose_f32<<<4096, dim3(32, 8)>>>(wq, wk, wv, wo, WTqkv, WTo);
    transpose_f16<<<8192, dim3(32, 8)>>>(w1, w2, WT1h, WT2h);
    concat_bias<<<12, 256>>>(bq, bk, bv, Bqkv);

    const int nX = MROWS * D_MODEL;
    round_tf32<<<nX/1024, 256>>>(x, Xr, nX);

    const dim3 blk(256);
    // fused QKV projection (tf32): [4096,1024] @ [1024,3072] -> QKV (tf32-rounded)
    gemm_tc<<<dim3(3072/128, MROWS/128), blk, GEMM_SMEM>>>(Xr, WTqkv, Bqkv, QKV,
                                                           MROWS, 3072, D_MODEL, 1);

    // tensor-core causal attention (tf32) -> CTX [B,S,1024] (tf32-rounded)
    attn_tc<<<dim3(SEQ/64, BATCH*NHEADS), 128, ATTN_SMEM>>>(
        QKV, QKV + 1024, QKV + 2048, CTX, 3072, D_MODEL);

    // out projection (tf32) + LN + residual (X1 fp32 + fp16 copy)
    gemm_tc<<<dim3(D_MODEL/128, MROWS/128), blk, GEMM_SMEM>>>(CTX, WTo, nullptr, PRJ,
                                                              MROWS, D_MODEL, D_MODEL, 0);
    ln_res_kernel<<<MROWS, 256>>>(PRJ, x, ln1_g, ln1_b, X1, X1h);

    // FFN (fp16 m16n8k16): FFN1 + exact GELU -> Hh (fp16); FFN2 -> T (fp32)
    gemm_f16<<<dim3(DHID/128, MROWS/128), blk>>>(X1h, WT1h, b1, nullptr, Hh,
                                                 MROWS, DHID, D_MODEL, 1);
    gemm_f16<<<dim3(D_MODEL/128, MROWS/128), blk>>>(Hh, WT2h, nullptr, T, nullptr,
                                                    MROWS, D_MODEL, DHID, 0);
    ln_res_kernel<<<MROWS, 256>>>(T, X1, ln2_g, ln2_b, out, nullptr);
}

// round 17
// speedup vs baseline: 1.3477x; 1.1222x over previous
#include <cuda_runtime.h>
#include <cuda_fp16.h>
#include <math.h>
#include <cstdint>

#define D_MODEL 1024
#define DHEAD   64
#define NHEADS  16
#define DHID    4096
#define BATCH   2
#define SEQ     2048
#define MROWS   (BATCH*SEQ)   // 4096
#define LN_EPS  1e-5f

// ---------------- scratch (device globals; no allocations allowed) ----------
__device__ float  g_QKV [(size_t)MROWS*3072];
__device__ __half g_CTXh[MROWS*D_MODEL];
__device__ float  g_PRJ [MROWS*D_MODEL];
__device__ float  g_X1  [MROWS*D_MODEL];
__device__ float  g_T   [MROWS*D_MODEL];
__device__ __half g_Xh  [MROWS*D_MODEL];
__device__ __half g_X1h [MROWS*D_MODEL];
__device__ __half g_Hh  [(size_t)MROWS*DHID];
__device__ __half g_WTqkvh[(size_t)3*D_MODEL*D_MODEL];
__device__ __half g_WToh[D_MODEL*D_MODEL];
__device__ __half g_WT1h[(size_t)DHID*D_MODEL];
__device__ __half g_WT2h[(size_t)D_MODEL*DHID];
__device__ float  g_Bqkv[3072];

// ---------------- small asm helpers ------------------------------------------
__device__ __forceinline__ uint32_t smem_u32(const void* p) {
    uint32_t a;
    asm("{ .reg .u64 t; cvta.to.shared.u64 t, %1; cvt.u32.u64 %0, t; }" : "=r"(a) : "l"(p));
    return a;
}
__device__ __forceinline__ void cp_async16(uint32_t s, const void* g) {
    asm volatile("cp.async.cg.shared.global [%0], [%1], 16;" :: "r"(s), "l"(g));
}
#define CP_COMMIT() asm volatile("cp.async.commit_group;")
#define CP_WAIT(N)  asm volatile("cp.async.wait_group %0;" :: "n"(N))

__device__ __forceinline__ void ldsm_x4(uint32_t* r, uint32_t addr) {
    asm volatile("ldmatrix.sync.aligned.m8n8.x4.shared.b16 {%0,%1,%2,%3}, [%4];"
        : "=r"(r[0]), "=r"(r[1]), "=r"(r[2]), "=r"(r[3]) : "r"(addr));
}
__device__ __forceinline__ void ldsm_x2(uint32_t* r, uint32_t addr) {
    asm volatile("ldmatrix.sync.aligned.m8n8.x2.shared.b16 {%0,%1}, [%2];"
        : "=r"(r[0]), "=r"(r[1]) : "r"(addr));
}

__device__ __forceinline__ float tf32r(float x) {
    float y;
    asm("cvt.rna.tf32.f32 %0, %1;" : "=f"(y) : "f"(x));
    return y;
}
__device__ __forceinline__ void mma_tf32u(float* d, const uint32_t* a, const uint32_t* b) {
    asm volatile(
        "mma.sync.aligned.m16n8k8.row.col.f32.tf32.tf32.f32 "
        "{%0,%1,%2,%3}, {%4,%5,%6,%7}, {%8,%9}, {%0,%1,%2,%3};"
        : "+f"(d[0]), "+f"(d[1]), "+f"(d[2]), "+f"(d[3])
        : "r"(a[0]), "r"(a[1]), "r"(a[2]), "r"(a[3]), "r"(b[0]), "r"(b[1]));
}
__device__ __forceinline__ void mma_f16u(float* d, const uint32_t* a, const uint32_t* b) {
    asm volatile(
        "mma.sync.aligned.m16n8k16.row.col.f32.f16.f16.f32 "
        "{%0,%1,%2,%3}, {%4,%5,%6,%7}, {%8,%9}, {%0,%1,%2,%3};"
        : "+f"(d[0]), "+f"(d[1]), "+f"(d[2]), "+f"(d[3])
        : "r"(a[0]), "r"(a[1]), "r"(a[2]), "r"(a[3]), "r"(b[0]), "r"(b[1]));
}

__device__ __forceinline__ float gelu_exact(float x) {
    return 0.5f * x * (1.0f + erff(x * 0.70710678118654752f));
}

// ---------------- fp16 mma.sync GEMM (m16n8k16) -------------------------------
// 128x128 tile, 8 warps (2x4), warp tile 64x32, BK=32 (2 k16 steps).
// Smem rows padded to 40 halves (80B): 16B-aligned, conflict-free ldsm.
#define HSROW 40

__global__ __launch_bounds__(256, 2)
void gemm_f16(const __half* __restrict__ A, const __half* __restrict__ BT,
              const float* __restrict__ bias, float* __restrict__ Cf,
              __half* __restrict__ Ch, int M, int N, int K, int act, int round_out)
{
    __shared__ __align__(16) __half As[2][128 * HSROW];
    __shared__ __align__(16) __half Bs[2][128 * HSROW];

    const int tid  = threadIdx.x;
    const int wid  = tid >> 5;
    const int lane = tid & 31;
    const int wm   = wid >> 2;    // 0..1 (64 rows each)
    const int wn   = wid & 3;     // 0..3 (32 cols each)
    const int row0 = blockIdx.y * 128;
    const int col0 = blockIdx.x * 128;

    const uint32_t sAu[2] = { smem_u32(As[0]), smem_u32(As[1]) };
    const uint32_t sBu[2] = { smem_u32(Bs[0]), smem_u32(Bs[1]) };

    const int a_row = (lane & 7) + 8 * ((lane >> 3) & 1);
    const int a_k   = 8 * (lane >> 4);
    const int b_row = lane & 7;
    const int b_k   = 8 * ((lane >> 3) & 1);

    uint32_t aoff[4];
    #pragma unroll
    for (int mt = 0; mt < 4; mt++)
        aoff[mt] = (uint32_t)((wm*64 + mt*16 + a_row) * HSROW + a_k) * 2;
    uint32_t boff[4];
    #pragma unroll
    for (int nt = 0; nt < 4; nt++)
        boff[nt] = (uint32_t)((wn*32 + nt*8 + b_row) * HSROW + b_k) * 2;

    float acc[4][4][4];
    #pragma unroll
    for (int i = 0; i < 4; i++)
        #pragma unroll
        for (int j = 0; j < 4; j++)
            #pragma unroll
            for (int q = 0; q < 4; q++) acc[i][j][q] = 0.0f;

    const int nChunks = K / 32;

    auto load_chunk = [&](int c, int st) {
        const int k0 = c * 32;
        #pragma unroll
        for (int i = 0; i < 2; i++) {
            const int idx = i * 256 + tid;          // 0..511
            const int r = idx >> 2, j = (idx & 3) * 8;
            cp_async16(sAu[st] + (uint32_t)(r * HSROW + j) * 2,
                       A + (size_t)(row0 + r) * K + k0 + j);
        }
        #pragma unroll
        for (int i = 0; i < 2; i++) {
            const int idx = i * 256 + tid;
            const int r = idx >> 2, j = (idx & 3) * 8;
            cp_async16(sBu[st] + (uint32_t)(r * HSROW + j) * 2,
                       BT + (size_t)(col0 + r) * K + k0 + j);
        }
        CP_COMMIT();
    };

    load_chunk(0, 0);

    for (int c = 0; c < nChunks; c++) {
        const int st = c & 1;
        if (c + 1 < nChunks) { load_chunk(c + 1, st ^ 1); CP_WAIT(1); }
        else                 { CP_WAIT(0); }
        __syncthreads();

        const uint32_t sa = sAu[st];
        const uint32_t sb = sBu[st];

        #pragma unroll
        for (int ks = 0; ks < 2; ks++) {
            uint32_t af[4][4], bfr[4][2];
            #pragma unroll
            for (int mt = 0; mt < 4; mt++)
                ldsm_x4(af[mt], sa + aoff[mt] + ks * 32);
            #pragma unroll
            for (int nt = 0; nt < 4; nt++)
                ldsm_x2(bfr[nt], sb + boff[nt] + ks * 32);
            #pragma unroll
            for (int mt = 0; mt < 4; mt++)
                #pragma unroll
                for (int nt = 0; nt < 4; nt++)
                    mma_f16u(acc[mt][nt], af[mt], bfr[nt]);
        }
        __syncthreads();
    }

    // ---- epilogue ----
    const int gr = lane >> 2;
    const int gc = (lane & 3) * 2;
    #pragma unroll
    for (int mt = 0; mt < 4; mt++) {
        #pragma unroll
        for (int nt = 0; nt < 4; nt++) {
            const int rA = row0 + wm * 64 + mt * 16 + gr;
            const int cA = col0 + wn * 32 + nt * 8 + gc;
            float b0 = 0.f, b1 = 0.f;
            if (bias) { b0 = bias[cA]; b1 = bias[cA + 1]; }
            float v00 = acc[mt][nt][0] + b0, v01 = acc[mt][nt][1] + b1;
            float v10 = acc[mt][nt][2] + b0, v11 = acc[mt][nt][3] + b1;
            if (act == 1) {
                v00 = gelu_exact(v00); v01 = gelu_exact(v01);
                v10 = gelu_exact(v10); v11 = gelu_exact(v11);
            }
            if (Cf) {
                float w00 = v00, w01 = v01, w10 = v10, w11 = v11;
                if (round_out) {
                    w00 = tf32r(w00); w01 = tf32r(w01);
                    w10 = tf32r(w10); w11 = tf32r(w11);
                }
                *(float2*)&Cf[(size_t)rA * N + cA]       = make_float2(w00, w01);
                *(float2*)&Cf[(size_t)(rA + 8) * N + cA] = make_float2(w10, w11);
            }
            if (Ch) {
                *(__half2*)&Ch[(size_t)rA * N + cA]       = __floats2half2_rn(v00, v01);
                *(__half2*)&Ch[(size_t)(rA + 8) * N + cA] = __floats2half2_rn(v10, v11);
            }
        }
    }
}

// ---------------- fp32 -> fp16 convert ----------------------------------------
__global__ void conv_f16(const float* __restrict__ in, __half* __restrict__ out, int n)
{
    const int i = (blockIdx.x * blockDim.x + threadIdx.x) * 4;
    if (i < n) {
        float4 v = *(const float4*)(in + i);
        *(__half2*)(out + i)     = __floats2half2_rn(v.x, v.y);
        *(__half2*)(out + i + 2) = __floats2half2_rn(v.z, v.w);
    }
}

// ---------------- all weight transposes (f32 [K,N] -> fp16 [N,K]) -------------
// blocks: [0,3072) wq/wk/wv; [3072,4096) wo; [4096,8192) w1; [8192,12288) w2
__global__ void transpose_all_f16(const float* __restrict__ wq, const float* __restrict__ wk,
                                  const float* __restrict__ wv, const float* __restrict__ wo,
                                  const float* __restrict__ w1, const float* __restrict__ w2,
                                  __half* __restrict__ WTqkvh, __half* __restrict__ WToh,
                                  __half* __restrict__ WT1h, __half* __restrict__ WT2h)
{
    const int idx = blockIdx.x;
    const float* W; __half* WT; int Nd, Kd, bx, by;
    if (idx < 3072) {
        const int w = idx >> 10, t = idx & 1023;
        W  = (w == 0) ? wq : (w == 1) ? wk : wv;
        WT = WTqkvh + (size_t)w * D_MODEL * D_MODEL;
        Nd = D_MODEL; Kd = D_MODEL; bx = (t & 31) * 32; by = (t >> 5) * 32;
    } else if (idx < 4096) {
        const int t = idx - 3072;
        W = wo; WT = WToh;
        Nd = D_MODEL; Kd = D_MODEL; bx = (t & 31) * 32; by = (t >> 5) * 32;
    } else if (idx < 8192) {
        const int t = idx - 4096;
        W = w1; WT = WT1h;
        Nd = DHID; Kd = D_MODEL; bx = (t & 127) * 32; by = (t >> 7) * 32;
    } else {
        const int t = idx - 8192;
        W = w2; WT = WT2h;
        Nd = D_MODEL; Kd = DHID; bx = (t & 31) * 32; by = (t >> 5) * 32;
    }

    __shared__ float tbuf[32][33];
    const int tx = threadIdx.x, ty = threadIdx.y;
    #pragma unroll
    for (int i = ty; i < 32; i += 8)
        tbuf[i][tx] = W[(size_t)(by + i) * Nd + bx + tx];
    __syncthreads();
    #pragma unroll
    for (int i = ty; i < 32; i += 8)
        WT[(size_t)(bx + i) * Kd + by + tx] = __float2half_rn(tbuf[tx][i]);
}

// ---------------- bias concat -------------------------------------------------
__global__ void concat_bias(const float* __restrict__ bq, const float* __restrict__ bk,
                            const float* __restrict__ bv, float* __restrict__ o)
{
    const int i = blockIdx.x * 256 + threadIdx.x;
    if (i < 1024)       o[i] = bq[i];
    else if (i < 2048)  o[i] = bk[i - 1024];
    else if (i < 3072)  o[i] = bv[i - 2048];
}

// ---------------- tensor-core flash attention (tf32, round-11 config) ---------
// Epilogue writes fp16 CTX for the fp16 WO GEMM.
#define KPAD 68
#define VPAD 72
#define ATTN_SMEM ((64*KPAD + 64*VPAD + 64*KPAD) * 4)

__global__ __launch_bounds__(128)
void attn_tc(const float* __restrict__ Qp, const float* __restrict__ Kp,
             const float* __restrict__ Vp, __half* __restrict__ O,
             int ldq, int ldo)
{
    extern __shared__ float sm[];
    float* Ks = sm;
    float* Vs = sm + 64 * KPAD;
    float* Ps = sm + 64 * KPAD + 64 * VPAD;
    const uint32_t ksu = smem_u32(Ks);
    const uint32_t psu = smem_u32(Ps);

    const int qt   = (int)gridDim.x - 1 - (int)blockIdx.x;
    const int bh   = blockIdx.y;
    const int b    = bh >> 4;
    const int h    = bh & 15;
    const int tid  = threadIdx.x;
    const int wid  = tid >> 5;
    const int lane = tid & 31;
    const int r0   = lane >> 2;
    const int c0   = lane & 3;
    const int m8   = lane >> 3;
    const int lr   = lane & 7;
    const int prow = wid * 16;

    uint32_t koff[8];
    #pragma unroll
    for (int nt = 0; nt < 8; nt++)
        koff[nt] = (uint32_t)((nt*8 + lr) * KPAD) * 4 + ((lane >> 3) & 1) * 16;
    const uint32_t poff = (uint32_t)((prow + (m8 & 1)*8 + lr) * KPAD) * 4 + (m8 >> 1) * 16;

    uint32_t qa[8][4];
    {
        const size_t qbase = ((size_t)(b * SEQ + qt * 64 + wid * 16)) * ldq + h * 64;
        #pragma unroll
        for (int ks = 0; ks < 8; ks++) {
            qa[ks][0] = __float_as_uint(Qp[qbase + (size_t)r0 * ldq + ks * 8 + c0] * 0.125f);
            qa[ks][1] = __float_as_uint(Qp[qbase + (size_t)(r0 + 8) * ldq + ks * 8 + c0] * 0.125f);
            qa[ks][2] = __float_as_uint(Qp[qbase + (size_t)r0 * ldq + ks * 8 + c0 + 4] * 0.125f);
            qa[ks][3] = __float_as_uint(Qp[qbase + (size_t)(r0 + 8) * ldq + ks * 8 + c0 + 4] * 0.125f);
        }
    }

    float o[8][4];
    #pragma unroll
    for (int nt = 0; nt < 8; nt++)
        #pragma unroll
        for (int q = 0; q < 4; q++) o[nt][q] = 0.0f;
    float mA = -1e30f, mB = -1e30f, lA = 0.0f, lB = 0.0f;

    const size_t kvbase = ((size_t)b * SEQ) * ldq + h * 64;

    for (int kt = 0; kt <= qt; kt++) {
        #pragma unroll
        for (int i = 0; i < 8; i++) {
            const int idx = i * 128 + tid;
            const int r   = idx >> 4;
            const int c4  = (idx & 15) << 2;
            const size_t src = kvbase + (size_t)(kt * 64 + r) * ldq + c4;
            *(float4*)&Ks[r * KPAD + c4] = *(const float4*)(Kp + src);
            *(float4*)&Vs[r * VPAD + c4] = *(const float4*)(Vp + src);
        }
        __syncthreads();

        float s[8][4];
        #pragma unroll
        for (int nt = 0; nt < 8; nt++)
            #pragma unroll
            for (int q = 0; q < 4; q++) s[nt][q] = 0.0f;

        #pragma unroll
        for (int ks = 0; ks < 8; ks++) {
            #pragma unroll
            for (int nt = 0; nt < 8; nt++) {
                uint32_t bfr[2];
                ldsm_x2(bfr, ksu + koff[nt] + ks * 32);
                mma_tf32u(s[nt], qa[ks], bfr);
            }
        }

        if (kt == qt) {
            const int rA = wid * 16 + r0;
            const int rB = rA + 8;
            #pragma unroll
            for (int nt = 0; nt < 8; nt++) {
                const int cc = nt * 8 + c0 * 2;
                if (cc     > rA) s[nt][0] = -1e30f;
                if (cc + 1 > rA) s[nt][1] = -1e30f;
                if (cc     > rB) s[nt][2] = -1e30f;
                if (cc + 1 > rB) s[nt][3] = -1e30f;
            }
        }

        float tmA = -1e30f, tmB = -1e30f;
        #pragma unroll
        for (int nt = 0; nt < 8; nt++) {
            tmA = fmaxf(tmA, fmaxf(s[nt][0], s[nt][1]));
            tmB = fmaxf(tmB, fmaxf(s[nt][2], s[nt][3]));
        }
        tmA = fmaxf(tmA, __shfl_xor_sync(0xffffffffu, tmA, 1));
        tmA = fmaxf(tmA, __shfl_xor_sync(0xffffffffu, tmA, 2));
        tmB = fmaxf(tmB, __shfl_xor_sync(0xffffffffu, tmB, 1));
        tmB = fmaxf(tmB, __shfl_xor_sync(0xffffffffu, tmB, 2));

        const float mnA = fmaxf(mA, tmA);
        const float mnB = fmaxf(mB, tmB);
        const float cA = __expf(mA - mnA);
        const float cB = __expf(mB - mnB);
        lA *= cA; lB *= cB;
        #pragma unroll
        for (int nt = 0; nt < 8; nt++) {
            o[nt][0] *= cA; o[nt][1] *= cA;
            o[nt][2] *= cB; o[nt][3] *= cB;
        }

        float sumA = 0.0f, sumB = 0.0f;
        #pragma unroll
        for (int nt = 0; nt < 8; nt++) {
            const float p0 = __expf(s[nt][0] - mnA);
            const float p1 = __expf(s[nt][1] - mnA);
            const float p2 = __expf(s[nt][2] - mnB);
            const float p3 = __expf(s[nt][3] - mnB);
            sumA += p0 + p1;
            sumB += p2 + p3;
            *(float2*)&Ps[(prow + r0) * KPAD + nt * 8 + c0 * 2]     = make_float2(tf32r(p0), tf32r(p1));
            *(float2*)&Ps[(prow + r0 + 8) * KPAD + nt * 8 + c0 * 2] = make_float2(tf32r(p2), tf32r(p3));
        }
        sumA += __shfl_xor_sync(0xffffffffu, sumA, 1);
        sumA += __shfl_xor_sync(0xffffffffu, sumA, 2);
        sumB += __shfl_xor_sync(0xffffffffu, sumB, 1);
        sumB += __shfl_xor_sync(0xffffffffu, sumB, 2);
        lA += sumA; lB += sumB;
        mA = mnA; mB = mnB;

        __syncwarp();

        #pragma unroll
        for (int ks = 0; ks < 8; ks++) {
            uint32_t af[4];
            ldsm_x4(af, psu + poff + ks * 32);
            #pragma unroll
            for (int nt = 0; nt < 8; nt++) {
                uint32_t bfr[2];
                bfr[0] = __float_as_uint(Vs[(ks * 8 + c0) * VPAD + nt * 8 + r0]);
                bfr[1] = __float_as_uint(Vs[(ks * 8 + c0 + 4) * VPAD + nt * 8 + r0]);
                mma_tf32u(o[nt], af, bfr);
            }
        }
        __syncthreads();
    }

    const float invA = 1.0f / lA;
    const float invB = 1.0f / lB;
    const size_t obase = ((size_t)(b * SEQ + qt * 64 + wid * 16)) * ldo + h * 64;
    #pragma unroll
    for (int nt = 0; nt < 8; nt++) {
        const int cc = nt * 8 + c0 * 2;
        *(__half2*)&O[obase + (size_t)r0 * ldo + cc] =
            __floats2half2_rn(o[nt][0] * invA, o[nt][1] * invA);
        *(__half2*)&O[obase + (size_t)(r0 + 8) * ldo + cc] =
            __floats2half2_rn(o[nt][2] * invB, o[nt][3] * invB);
    }
}

// ---------------- fused LayerNorm + residual add -----------------------------
__global__ void ln_res_kernel(const float* __restrict__ inp, const float* __restrict__ resid,
                              const float* __restrict__ gam, const float* __restrict__ bet,
                              float* __restrict__ out, __half* __restrict__ out_h)
{
    const int row = blockIdx.x;
    const int tid = threadIdx.x;
    const float* v = inp + (size_t)row * D_MODEL;

    float vals[4];
    float s = 0.0f;
    #pragma unroll
    for (int i = 0; i < 4; i++) { vals[i] = v[tid + 256 * i]; s += vals[i]; }

    __shared__ float red1[8];
    __shared__ float red2[8];
    const int lane = tid & 31, w = tid >> 5;

    #pragma unroll
    for (int o = 16; o > 0; o >>= 1) s += __shfl_xor_sync(0xffffffffu, s, o);
    if (lane == 0) red1[w] = s;
    __syncthreads();
    float mu = 0.0f;
    #pragma unroll
    for (int i = 0; i < 8; i++) mu += red1[i];
    mu *= (1.0f / D_MODEL);

    float vs = 0.0f;
    #pragma unroll
    for (int i = 0; i < 4; i++) { float d = vals[i] - mu; vs += d * d; }
    #pragma unroll
    for (int o = 16; o > 0; o >>= 1) vs += __shfl_xor_sync(0xffffffffu, vs, o);
    if (lane == 0) red2[w] = vs;
    __syncthreads();
    float var = 0.0f;
    #pragma unroll
    for (int i = 0; i < 8; i++) var += red2[i];
    var *= (1.0f / D_MODEL);
    const float rs = rsqrtf(var + LN_EPS);

    #pragma unroll
    for (int i = 0; i < 4; i++) {
        const int idx = tid + 256 * i;
        const size_t off = (size_t)row * D_MODEL + idx;
        const float o = resid[off] + (vals[i] - mu) * rs * gam[idx] + bet[idx];
        out[off] = o;
        if (out_h) out_h[off] = __float2half_rn(o);
    }
}

// ---------------- launch -----------------------------------------------------
extern "C" void kernel_launch(void* const* d_in, const int* in_sizes, int n_in,
                              void* d_out, int out_size)
{
    const float* x     = (const float*)d_in[0];
    const float* wq    = (const float*)d_in[1];
    const float* bq    = (const float*)d_in[2];
    const float* wk    = (const float*)d_in[3];
    const float* bk    = (const float*)d_in[4];
    const float* wv    = (const float*)d_in[5];
    const float* bv    = (const float*)d_in[6];
    const float* wo    = (const float*)d_in[7];
    const float* ln1_g = (const float*)d_in[8];
    const float* ln1_b = (const float*)d_in[9];
    const float* w1    = (const float*)d_in[10];
    const float* b1    = (const float*)d_in[11];
    const float* w2    = (const float*)d_in[12];
    const float* ln2_g = (const float*)d_in[13];
    const float* ln2_b = (const float*)d_in[14];
    float* out = (float*)d_out;

    void *pQKV, *pCTXh, *pPRJ, *pX1, *pT, *pXh, *pX1h, *pHh;
    void *pWTqkvh, *pWToh, *pWT1h, *pWT2h, *pBqkv;
    cudaGetSymbolAddress(&pQKV,   g_QKV);
    cudaGetSymbolAddress(&pCTXh,  g_CTXh);
    cudaGetSymbolAddress(&pPRJ,   g_PRJ);
    cudaGetSymbolAddress(&pX1,    g_X1);
    cudaGetSymbolAddress(&pT,     g_T);
    cudaGetSymbolAddress(&pXh,    g_Xh);
    cudaGetSymbolAddress(&pX1h,   g_X1h);
    cudaGetSymbolAddress(&pHh,    g_Hh);
    cudaGetSymbolAddress(&pWTqkvh,g_WTqkvh);
    cudaGetSymbolAddress(&pWToh,  g_WToh);
    cudaGetSymbolAddress(&pWT1h,  g_WT1h);
    cudaGetSymbolAddress(&pWT2h,  g_WT2h);
    cudaGetSymbolAddress(&pBqkv,  g_Bqkv);
    float*  QKV   = (float*)pQKV;    __half* CTXh = (__half*)pCTXh;
    float*  PRJ   = (float*)pPRJ;    float*  X1   = (float*)pX1;
    float*  T     = (float*)pT;      __half* Xh   = (__half*)pXh;
    __half* X1h   = (__half*)pX1h;   __half* Hh   = (__half*)pHh;
    __half* WTqkvh= (__half*)pWTqkvh;__half* WToh = (__half*)pWToh;
    __half* WT1h  = (__half*)pWT1h;  __half* WT2h = (__half*)pWT2h;
    float*  Bqkv  = (float*)pBqkv;

    cudaFuncSetAttribute(attn_tc, cudaFuncAttributeMaxDynamicSharedMemorySize, ATTN_SMEM);

    transpose_all_f16<<<12288, dim3(32, 8)>>>(wq, wk, wv, wo, w1, w2,
                                              WTqkvh, WToh, WT1h, WT2h);
    concat_bias<<<12, 256>>>(bq, bk, bv, Bqkv);

    const int nX = MROWS * D_MODEL;
    conv_f16<<<nX/1024, 256>>>(x, Xh, nX);

    const dim3 blk(256);
    // fused QKV projection (fp16 MMA, fp32+tf32-rounded out for tf32 attention)
    gemm_f16<<<dim3(3072/128, MROWS/128), blk>>>(Xh, WTqkvh, Bqkv, QKV, nullptr,
                                                 MROWS, 3072, D_MODEL, 0, 1);

    // tensor-core causal attention (tf32) -> CTXh (fp16)
    attn_tc<<<dim3(SEQ/64, BATCH*NHEADS), 128, ATTN_SMEM>>>(
        QKV, QKV + 1024, QKV + 2048, CTXh, 3072, D_MODEL);

    // out projection (fp16) + LN + residual (X1 fp32 + fp16 copy)
    gemm_f16<<<dim3(D_MODEL/128, MROWS/128), blk>>>(CTXh, WToh, nullptr, PRJ, nullptr,
                                                    MROWS, D_MODEL, D_MODEL, 0, 0);
    ln_res_kernel<<<MROWS, 256>>>(PRJ, x, ln1_g, ln1_b, X1, X1h);

    // FFN (fp16): FFN1 + exact GELU -> Hh; FFN2 -> T (fp32)
    gemm_f16<<<dim3(DHID/128, MROWS/128), blk>>>(X1h, WT1h, b1, nullptr, Hh,
                                                 MROWS, DHID, D_MODEL, 1, 0);
    gemm_f16<<<dim3(D_MODEL/128, MROWS/128), blk>>>(Hh, WT2h, nullptr, T, nullptr,
                                                    MROWS, D_MODEL, DHID, 0, 0);
    ln_res_kernel<<<MROWS, 256>>>(T, X1, ln2_g, ln2_b, out, nullptr);
}